// round 11
// baseline (speedup 1.0000x reference)
#include <cuda_runtime.h>
#include <stdint.h>

// out[i,j] = 2*x[i,j] + 5 - (i+j), x: [8192, 8192] fp32.
//
// Flat-grid HBM-streaming kernel at the measured machine ceiling
// (~6.5 TB/s, ~81.5% of 8 TB/s spec; compute pipes <6%).
// Measured: UNROLL {1,4,8} -> 4; threads 256 -> 512 gained ~0.3us via longer
// contiguous per-CTA extents; flat grid >> persistent; __ldcs/__stcs best.
// This round: THREADS=1024 (64KB contiguous per CTA, 4096 blocks; occupancy
// unchanged at 64 warps/SM with regs=28) — last untested block-shape cell.

#define N_DIM 8192
#define M_DIM 8192
#define VEC_PER_ROW_LOG2 11             // 8192/4 = 2048 float4 per row
#define VEC_PER_ROW (1 << VEC_PER_ROW_LOG2)
#define UNROLL 4
#define THREADS 1024

__global__ __launch_bounds__(THREADS) void fused_affine_outer_kernel(
    const float4* __restrict__ x, float4* __restrict__ out)
{
    // Each block owns a contiguous chunk of UNROLL*THREADS vectors;
    // within each unroll step the warp's accesses are fully coalesced.
    unsigned int base = blockIdx.x * (THREADS * UNROLL) + threadIdx.x;

    float4 in[UNROLL];
#pragma unroll
    for (int k = 0; k < UNROLL; k++) {
        in[k] = __ldcs(&x[base + k * THREADS]);
    }

#pragma unroll
    for (int k = 0; k < UNROLL; k++) {
        unsigned int v  = base + k * THREADS;
        unsigned int i  = v >> VEC_PER_ROW_LOG2;          // row
        unsigned int j4 = (v & (VEC_PER_ROW - 1)) << 2;   // col of lane 0
        float b = 5.0f - (float)(i + j4);

        float4 o;
        o.x = fmaf(in[k].x, 2.0f, b);
        o.y = fmaf(in[k].y, 2.0f, b - 1.0f);
        o.z = fmaf(in[k].z, 2.0f, b - 2.0f);
        o.w = fmaf(in[k].w, 2.0f, b - 3.0f);
        __stcs(&out[v], o);
    }
}

extern "C" void kernel_launch(void* const* d_in, const int* in_sizes, int n_in,
                              void* d_out, int out_size)
{
    const float4* x = (const float4*)d_in[0];
    float4* out = (float4*)d_out;

    const unsigned int total_vec = (N_DIM * M_DIM) / 4;         // 16,777,216
    const unsigned int blocks = total_vec / (THREADS * UNROLL); // 4,096

    fused_affine_outer_kernel<<<blocks, THREADS>>>(x, out);
}

// round 12
// speedup vs baseline: 1.0012x; 1.0012x over previous
#include <cuda_runtime.h>
#include <stdint.h>

// out[i,j] = 2*x[i,j] + 5 - (i+j), x: [8192, 8192] fp32.
//
// FINAL KERNEL — flat-grid HBM-streaming at the measured machine ceiling:
// ~6.5 TB/s (~82% of 8 TB/s spec), DRAM pipe ~82% busy, compute pipes <6%.
//
// Full design space measured (11 benched rounds, all passing, rel_err 1.3e-9):
//   UNROLL:    1 -> 82.2us | 4 -> 81.7us (BEST) | 8 -> 82.6us (occ 78->61%)
//   threads:   256 -> 82.0 | 512 -> 81.7 (BEST harness) | 1024 -> 82.0
//              (1024 gives best ncu kernel-dur 73.3us / DRAM 82.9% but no
//               harness gain — extent trend saturates at 512)
//   schedule:  flat grid (BEST) | persistent 1-wave grid-stride -> 92.9us
//              (per-CTA loop serializes next loads behind prior stores)
//   loads:     __ldcs (BEST) | __ldcg neutral (l1tex never binding)
//   stores:    __stcs (BEST) | __stwt -> 82.9us (loses L2 write-combining)
// Traffic is minimal (1R+1W per element, fully-coalesced 128B transactions);
// TMA/smem staging cannot beat direct LDG/STG (B300 LTS-cap path-independent).
//
// Config: 512 threads, 4x front-batched float4 loads per thread (MLP=4),
// __ldcs/__stcs evict-first hints (zero reuse), exact-cover 8192-block grid.

#define N_DIM 8192
#define M_DIM 8192
#define VEC_PER_ROW_LOG2 11             // 8192/4 = 2048 float4 per row
#define VEC_PER_ROW (1 << VEC_PER_ROW_LOG2)
#define UNROLL 4
#define THREADS 512

__global__ __launch_bounds__(THREADS) void fused_affine_outer_kernel(
    const float4* __restrict__ x, float4* __restrict__ out)
{
    // Each block owns a contiguous chunk of UNROLL*THREADS vectors;
    // within each unroll step the warp's accesses are fully coalesced.
    unsigned int base = blockIdx.x * (THREADS * UNROLL) + threadIdx.x;

    float4 in[UNROLL];
#pragma unroll
    for (int k = 0; k < UNROLL; k++) {
        in[k] = __ldcs(&x[base + k * THREADS]);
    }

#pragma unroll
    for (int k = 0; k < UNROLL; k++) {
        unsigned int v  = base + k * THREADS;
        unsigned int i  = v >> VEC_PER_ROW_LOG2;          // row
        unsigned int j4 = (v & (VEC_PER_ROW - 1)) << 2;   // col of lane 0
        float b = 5.0f - (float)(i + j4);

        float4 o;
        o.x = fmaf(in[k].x, 2.0f, b);
        o.y = fmaf(in[k].y, 2.0f, b - 1.0f);
        o.z = fmaf(in[k].z, 2.0f, b - 2.0f);
        o.w = fmaf(in[k].w, 2.0f, b - 3.0f);
        __stcs(&out[v], o);
    }
}

extern "C" void kernel_launch(void* const* d_in, const int* in_sizes, int n_in,
                              void* d_out, int out_size)
{
    const float4* x = (const float4*)d_in[0];
    float4* out = (float4*)d_out;

    const unsigned int total_vec = (N_DIM * M_DIM) / 4;         // 16,777,216
    const unsigned int blocks = total_vec / (THREADS * UNROLL); // 8,192

    fused_affine_outer_kernel<<<blocks, THREADS>>>(x, out);
}